// round 6
// baseline (speedup 1.0000x reference)
#include <cuda_runtime.h>
#include <cstdint>

#define D_MODEL 2048
#define N_HEADS 16
#define D_HEAD  128
#define SEQ     2048
#define BATCH   2
#define BS      (BATCH * SEQ)      // 4096
#define QKV_N   (3 * D_MODEL)      // 6144

// Scratch (allocation-free rule: __device__ globals)
__device__ float g_qkv[(size_t)BS * QKV_N];          // 96 MB (tf32, rounded)
__device__ float g_att[(size_t)BS * D_MODEL];        // 32 MB (tf32, rounded)
__device__ float g_x[(size_t)BS * D_MODEL];          // 32 MB (tf32-rounded x)
__device__ float g_wqkvT[(size_t)QKV_N * D_MODEL];   // 48 MB (W_qkv^T, rounded)
__device__ float g_woutT[(size_t)D_MODEL * D_MODEL]; // 16 MB (W_out^T, rounded)

__device__ __forceinline__ float tf32r(float x) {
    asm("cvt.rna.tf32.f32 %0, %1;" : "=f"(x) : "f"(x));
    return x;
}

__device__ __forceinline__ uint32_t smem_u32(const void* p) {
    uint32_t a;
    asm("{ .reg .u64 t; cvta.to.shared.u64 t, %1; cvt.u32.u64 %0, t; }" : "=r"(a) : "l"(p));
    return a;
}

__device__ __forceinline__ void mma8(float d[4], const uint32_t a[4], const uint32_t b[2]) {
    asm volatile(
        "mma.sync.aligned.m16n8k8.row.col.f32.tf32.tf32.f32 "
        "{%0,%1,%2,%3}, {%4,%5,%6,%7}, {%8,%9}, {%0,%1,%2,%3};\n"
        : "+f"(d[0]), "+f"(d[1]), "+f"(d[2]), "+f"(d[3])
        : "r"(a[0]), "r"(a[1]), "r"(a[2]), "r"(a[3]), "r"(b[0]), "r"(b[1]));
}

#define LDSM4(R0, R1, R2, R3, ADDR) \
    asm volatile("ldmatrix.sync.aligned.m8n8.x4.shared.b16 {%0,%1,%2,%3}, [%4];" \
                 : "=r"(R0), "=r"(R1), "=r"(R2), "=r"(R3) : "r"(ADDR))

__device__ __forceinline__ void cpasync16(uint32_t dst, const void* src) {
    asm volatile("cp.async.cg.shared.global [%0], [%1], 16;" :: "r"(dst), "l"(src) : "memory");
}
__device__ __forceinline__ void cp_commit() {
    asm volatile("cp.async.commit_group;" ::: "memory");
}
__device__ __forceinline__ void cp_wait0() {
    asm volatile("cp.async.wait_group 0;" ::: "memory");
}
__device__ __forceinline__ void cp_wait1() {
    asm volatile("cp.async.wait_group 1;" ::: "memory");
}

// ============================================================================
// Prep kernels
// ============================================================================
__global__ void round_copy4(const float* __restrict__ in, float* __restrict__ out, int n4) {
    int i = blockIdx.x * blockDim.x + threadIdx.x;
    if (i < n4) {
        float4 v = ((const float4*)in)[i];
        v.x = tf32r(v.x); v.y = tf32r(v.y); v.z = tf32r(v.z); v.w = tf32r(v.w);
        ((float4*)out)[i] = v;
    }
}

__global__ void transpose_round(const float* __restrict__ W, float* __restrict__ Wt,
                                int K, int N) {
    __shared__ float t[32][33];
    int n0 = blockIdx.x * 32, k0 = blockIdx.y * 32;
    int tx = threadIdx.x, ty = threadIdx.y;
#pragma unroll
    for (int i = ty; i < 32; i += 8)
        t[i][tx] = tf32r(W[(size_t)(k0 + i) * N + n0 + tx]);
    __syncthreads();
#pragma unroll
    for (int i = ty; i < 32; i += 8)
        Wt[(size_t)(n0 + i) * K + k0 + tx] = t[tx][i];
}

// ============================================================================
// tf32 GEMM: 512 threads, 16 warps (4x4), warp tile 32x32, 3-stage cp.async.
// C[M,N] = A[M,K] @ Bt[N,K]^T + bias[N].  Block tile 128x128x32.
// Regs capped at 64 -> 2 CTAs/SM -> 32 warps/SM (8/SMSP) for latency hiding.
// ============================================================================
#define GAF 4608                       // 128*36 floats per operand tile
#define G_STAGE_BYTES (2u * GAF * 4u)  // 36864
#define G_SMEM_BYTES (3u * G_STAGE_BYTES)   // 110592

__global__ __launch_bounds__(512, 2) void gemm_lm(
    const float* __restrict__ A, const float* __restrict__ Bt,
    const float* __restrict__ bias, float* __restrict__ C,
    int M, int N, int K, int round_out)
{
    extern __shared__ float smem[];
    const uint32_t sbase = smem_u32(smem);

    const int tid  = threadIdx.x;
    const int lane = tid & 31;
    const int wid  = tid >> 5;        // 0..15
    const int wm   = wid >> 2;        // 0..3  (32-row slice)
    const int wn   = wid & 3;         // 0..3  (32-col slice)
    const int g    = lane >> 2;
    const int tig  = lane & 3;

    const int m0 = blockIdx.y * 128;
    const int n0 = blockIdx.x * 128;
    const float* Ag = A + (size_t)m0 * K;
    const float* Bg = Bt + (size_t)n0 * K;
    const int nslab = K >> 5;

    // cp.async mapping: 512 threads, each thread 2x16B per operand
    const int crow = tid >> 2;        // 0..127
    const int ccj  = (tid & 3) * 8;   // 0,8,16,24 (float col)

    const int lmrow = lane & 15;
    const int lmc4  = (lane >> 4) * 4;
    const uint32_t a_lm = sbase + (((wm * 32 + lmrow) * 36 + lmc4) << 2);
    const uint32_t b_lm = sbase + (uint32_t)(GAF * 4) + (((wn * 32 + lmrow) * 36 + lmc4) << 2);

    float acc[2][4][4];
#pragma unroll
    for (int mt = 0; mt < 2; mt++)
#pragma unroll
        for (int nt = 0; nt < 4; nt++)
#pragma unroll
            for (int i = 0; i < 4; i++) acc[mt][nt][i] = 0.f;

    auto load_slab = [&](int i, int s) {
        const uint32_t ab = sbase + (uint32_t)s * G_STAGE_BYTES;
        const uint32_t bb = ab + (uint32_t)(GAF * 4);
        const int k0 = i << 5;
        cpasync16(ab + ((crow * 36 + ccj) << 2),     Ag + (size_t)crow * K + k0 + ccj);
        cpasync16(ab + ((crow * 36 + ccj + 4) << 2), Ag + (size_t)crow * K + k0 + ccj + 4);
        cpasync16(bb + ((crow * 36 + ccj) << 2),     Bg + (size_t)crow * K + k0 + ccj);
        cpasync16(bb + ((crow * 36 + ccj + 4) << 2), Bg + (size_t)crow * K + k0 + ccj + 4);
        cp_commit();
    };

    load_slab(0, 0);
    load_slab(1, 1);

    int s_c = 0;
    int s_l = 2;
    for (int i = 0; i < nslab; i++) {
        cp_wait1();
        __syncthreads();
        if (i + 2 < nslab) load_slab(i + 2, s_l);
        else cp_commit();

        const uint32_t a_st = a_lm + (uint32_t)s_c * G_STAGE_BYTES;
        const uint32_t b_st = b_lm + (uint32_t)s_c * G_STAGE_BYTES;
#pragma unroll
        for (int ks = 0; ks < 4; ks++) {
            const uint32_t ka = a_st + ks * 32;
            uint32_t af0[4], af1[4];
            LDSM4(af0[0], af0[1], af0[2], af0[3], ka);
            LDSM4(af1[0], af1[1], af1[2], af1[3], ka + 2304);  // +16 rows
            const uint32_t kb = b_st + ks * 32;
#pragma unroll
            for (int q = 0; q < 2; q++) {
                uint32_t b0, b1, b2, b3;
                LDSM4(b0, b1, b2, b3, kb + q * 2304);
                uint32_t bfA[2] = { b0, b2 };
                uint32_t bfB[2] = { b1, b3 };
                mma8(acc[0][2 * q],     af0, bfA);
                mma8(acc[0][2 * q + 1], af0, bfB);
                mma8(acc[1][2 * q],     af1, bfA);
                mma8(acc[1][2 * q + 1], af1, bfB);
            }
        }
        s_c++; if (s_c == 3) s_c = 0;
        s_l++; if (s_l == 3) s_l = 0;
    }

#pragma unroll
    for (int mt = 0; mt < 2; mt++) {
        int r = m0 + wm * 32 + mt * 16 + g;
#pragma unroll
        for (int nt = 0; nt < 4; nt++) {
            int c = n0 + wn * 32 + nt * 8 + tig * 2;
            float b0 = bias[c], b1 = bias[c + 1];
            float v0 = acc[mt][nt][0] + b0;
            float v1 = acc[mt][nt][1] + b1;
            float v2 = acc[mt][nt][2] + b0;
            float v3 = acc[mt][nt][3] + b1;
            if (round_out) { v0 = tf32r(v0); v1 = tf32r(v1); v2 = tf32r(v2); v3 = tf32r(v3); }
            *(float2*)(C + (size_t)r * N + c)       = make_float2(v0, v1);
            *(float2*)(C + (size_t)(r + 8) * N + c) = make_float2(v2, v3);
        }
    }
}

// ============================================================================
// Flash attention (causal): cp.async Q + double-buffered K, register-pipelined V.
// (unchanged from R5)
// ============================================================================
#define LDQ 132
#define LDV 68
#define ATTN_SMEM_FLOATS (128 * LDQ + 2 * 64 * LDQ + 128 * LDV + 128 * LDV)
#define ATTN_SMEM_BYTES (ATTN_SMEM_FLOATS * 4)

__global__ __launch_bounds__(256) void attn_kernel(
    const float* __restrict__ qkv, float* __restrict__ out)
{
    extern __shared__ float sm[];
    float* Vst = sm + 128 * LDQ + 2 * 64 * LDQ;
    float* Ps  = Vst + 128 * LDV;

    const int tid  = threadIdx.x;
    const int lane = tid & 31;
    const int wid  = tid >> 5;
    const int g    = lane >> 2;
    const int tig  = lane & 3;
    const int rbase = wid * 16;
    const int r1 = rbase + g;
    const int r2 = r1 + 8;

    const int qt = blockIdx.x;
    const int h  = blockIdx.y;
    const int b  = blockIdx.z;
    const int q0 = qt * 128;

    const float scale = 0.08838834764831845f; // 1/sqrt(128)
    const float* Qg = qkv + (size_t)b * SEQ * QKV_N + h * D_HEAD;
    const float* Kg = Qg + D_MODEL;
    const float* Vg = Qg + 2 * D_MODEL;

    const int lmrow = lane & 15;
    const int lmc4  = (lane >> 4) * 4;
    const uint32_t sb = smem_u32(sm);
    const uint32_t q_lm  = sb + (((rbase + lmrow) * LDQ + lmc4) << 2);
    const uint32_t k_lm0 = sb + ((128 * LDQ + lmrow * LDQ + lmc4) << 2);
    const uint32_t v_lm  = sb + (((128 + 128) * LDQ + lmrow * LDV + lmc4) << 2);
    const uint32_t p_lm  = sb + (((128 + 128) * LDQ + 128 * LDV + (rbase + lmrow) * LDV + lmc4) << 2);

    const int vn  = tid & 127;
    const int vk4 = tid >> 7;

    auto load_q = [&]() {
        for (int i = tid; i < 128 * 32; i += 256) {
            int r = i >> 5;
            int c = (i & 31) * 4;
            cpasync16(sb + ((r * LDQ + c) << 2), Qg + (size_t)(q0 + r) * QKV_N + c);
        }
    };
    auto load_k = [&](int j, int buf) {
        const int kb = j * 64;
        const uint32_t kbase = sb + ((128 * LDQ + buf * 64 * LDQ) << 2);
        for (int i = tid; i < 64 * 32; i += 256) {
            int r = i >> 5;
            int c = (i & 31) * 4;
            cpasync16(kbase + ((r * LDQ + c) << 2), Kg + (size_t)(kb + r) * QKV_N + c);
        }
    };

    load_q();
    load_k(0, 0);
    cp_commit();

    float o[16][4];
#pragma unroll
    for (int nt = 0; nt < 16; nt++)
#pragma unroll
        for (int i = 0; i < 4; i++) o[nt][i] = 0.f;
    float m1 = -1e30f, m2 = -1e30f, l1 = 0.f, l2 = 0.f;

    const int njt = 2 * qt + 2;

    float4 vr[8];
#pragma unroll
    for (int t = 0; t < 8; t++) {
        int k4 = vk4 + t * 2;
        vr[t].x = Vg[(size_t)(k4 * 4 + 0) * QKV_N + vn];
        vr[t].y = Vg[(size_t)(k4 * 4 + 1) * QKV_N + vn];
        vr[t].z = Vg[(size_t)(k4 * 4 + 2) * QKV_N + vn];
        vr[t].w = Vg[(size_t)(k4 * 4 + 3) * QKV_N + vn];
    }

    for (int j = 0; j < njt; j++) {
        cp_wait0();
        __syncthreads();

#pragma unroll
        for (int t = 0; t < 8; t++)
            *(float4*)(Vst + vn * LDV + (vk4 + t * 2) * 4) = vr[t];

        if (j + 1 < njt) load_k(j + 1, (j + 1) & 1);
        cp_commit();
        __syncthreads();

        if (j + 1 < njt) {
            const float* Vt = Vg + (size_t)(j + 1) * 64 * QKV_N;
#pragma unroll
            for (int t = 0; t < 8; t++) {
                int k4 = vk4 + t * 2;
                vr[t].x = Vt[(size_t)(k4 * 4 + 0) * QKV_N + vn];
                vr[t].y = Vt[(size_t)(k4 * 4 + 1) * QKV_N + vn];
                vr[t].z = Vt[(size_t)(k4 * 4 + 2) * QKV_N + vn];
                vr[t].w = Vt[(size_t)(k4 * 4 + 3) * QKV_N + vn];
            }
        }

        const uint32_t k_lm = k_lm0 + ((j & 1) ? (uint32_t)(64 * LDQ * 4) : 0u);
        float s[8][4];
#pragma unroll
        for (int nt = 0; nt < 8; nt++)
#pragma unroll
            for (int i = 0; i < 4; i++) s[nt][i] = 0.f;

#pragma unroll
        for (int ks = 0; ks < 16; ks++) {
            uint32_t af[4];
            LDSM4(af[0], af[1], af[2], af[3], q_lm + ks * 32);
            const uint32_t kbb = k_lm + ks * 32;
#pragma unroll
            for (int q = 0; q < 4; q++) {
                uint32_t b0, b1, b2, b3;
                LDSM4(b0, b1, b2, b3, kbb + q * (16 * LDQ * 4));
                uint32_t bfA[2] = { b0, b2 };
                uint32_t bfB[2] = { b1, b3 };
                mma8(s[2 * q],     af, bfA);
                mma8(s[2 * q + 1], af, bfB);
            }
        }

#pragma unroll
        for (int nt = 0; nt < 8; nt++) {
            s[nt][0] *= scale; s[nt][1] *= scale;
            s[nt][2] *= scale; s[nt][3] *= scale;
        }

        if (j >= 2 * qt) {
            const int koff = (j - 2 * qt) << 6;
            const int lim1 = r1 - koff;
            const int lim2 = r2 - koff;
#pragma unroll
            for (int nt = 0; nt < 8; nt++) {
                int c0 = nt * 8 + tig * 2;
                if (c0     > lim1) s[nt][0] = -1e30f;
                if (c0 + 1 > lim1) s[nt][1] = -1e30f;
                if (c0     > lim2) s[nt][2] = -1e30f;
                if (c0 + 1 > lim2) s[nt][3] = -1e30f;
            }
        }

        float mx1 = -1e30f, mx2 = -1e30f;
#pragma unroll
        for (int nt = 0; nt < 8; nt++) {
            mx1 = fmaxf(mx1, fmaxf(s[nt][0], s[nt][1]));
            mx2 = fmaxf(mx2, fmaxf(s[nt][2], s[nt][3]));
        }
        mx1 = fmaxf(mx1, __shfl_xor_sync(0xffffffffu, mx1, 1));
        mx1 = fmaxf(mx1, __shfl_xor_sync(0xffffffffu, mx1, 2));
        mx2 = fmaxf(mx2, __shfl_xor_sync(0xffffffffu, mx2, 1));
        mx2 = fmaxf(mx2, __shfl_xor_sync(0xffffffffu, mx2, 2));

        const float mn1 = fmaxf(m1, mx1);
        const float mn2 = fmaxf(m2, mx2);
        const float al1 = __expf(m1 - mn1);
        const float al2 = __expf(m2 - mn2);

        float sm1 = 0.f, sm2 = 0.f;
#pragma unroll
        for (int nt = 0; nt < 8; nt++) {
            s[nt][0] = __expf(s[nt][0] - mn1);
            s[nt][1] = __expf(s[nt][1] - mn1);
            s[nt][2] = __expf(s[nt][2] - mn2);
            s[nt][3] = __expf(s[nt][3] - mn2);
            sm1 += s[nt][0] + s[nt][1];
            sm2 += s[nt][2] + s[nt][3];
        }
        sm1 += __shfl_xor_sync(0xffffffffu, sm1, 1);
        sm1 += __shfl_xor_sync(0xffffffffu, sm1, 2);
        sm2 += __shfl_xor_sync(0xffffffffu, sm2, 1);
        sm2 += __shfl_xor_sync(0xffffffffu, sm2, 2);

        l1 = al1 * l1 + sm1;
        l2 = al2 * l2 + sm2;
        m1 = mn1;
        m2 = mn2;

#pragma unroll
        for (int nt = 0; nt < 16; nt++) {
            o[nt][0] *= al1; o[nt][1] *= al1;
            o[nt][2] *= al2; o[nt][3] *= al2;
        }

#pragma unroll
        for (int nt = 0; nt < 8; nt++) {
            int c = nt * 8 + tig * 2;
            *(float2*)(Ps + r1 * LDV + c) = make_float2(tf32r(s[nt][0]), tf32r(s[nt][1]));
            *(float2*)(Ps + r2 * LDV + c) = make_float2(tf32r(s[nt][2]), tf32r(s[nt][3]));
        }
        __syncwarp();

#pragma unroll
        for (int ks = 0; ks < 8; ks++) {
            uint32_t af[4];
            LDSM4(af[0], af[1], af[2], af[3], p_lm + ks * 32);
            const uint32_t vb = v_lm + ks * 32;
#pragma unroll
            for (int q = 0; q < 8; q++) {
                uint32_t b0, b1, b2, b3;
                LDSM4(b0, b1, b2, b3, vb + q * (16 * LDV * 4));
                uint32_t bfA[2] = { b0, b2 };
                uint32_t bfB[2] = { b1, b3 };
                mma8(o[2 * q],     af, bfA);
                mma8(o[2 * q + 1], af, bfB);
            }
        }
        __syncwarp();
    }

    const float inv1 = 1.f / l1;
    const float inv2 = 1.f / l2;
    float* Og = out + ((size_t)b * SEQ + q0) * D_MODEL + h * D_HEAD;
#pragma unroll
    for (int nt = 0; nt < 16; nt++) {
        int c = nt * 8 + tig * 2;
        *(float2*)(Og + (size_t)r1 * D_MODEL + c) =
            make_float2(tf32r(o[nt][0] * inv1), tf32r(o[nt][1] * inv1));
        *(float2*)(Og + (size_t)r2 * D_MODEL + c) =
            make_float2(tf32r(o[nt][2] * inv2), tf32r(o[nt][3] * inv2));
    }
}

// ============================================================================
// Launch
// ============================================================================
extern "C" void kernel_launch(void* const* d_in, const int* in_sizes, int n_in,
                              void* d_out, int out_size) {
    const float* x    = (const float*)d_in[0];
    const float* Wqkv = (const float*)d_in[1];
    const float* bqkv = (const float*)d_in[2];
    const float* Wout = (const float*)d_in[3];
    const float* bout = (const float*)d_in[4];
    float* out = (float*)d_out;

    float *qkv_p, *att_p, *x_p, *wqkvT_p, *woutT_p;
    cudaGetSymbolAddress((void**)&qkv_p, g_qkv);
    cudaGetSymbolAddress((void**)&att_p, g_att);
    cudaGetSymbolAddress((void**)&x_p, g_x);
    cudaGetSymbolAddress((void**)&wqkvT_p, g_wqkvT);
    cudaGetSymbolAddress((void**)&woutT_p, g_woutT);

    cudaFuncSetAttribute(gemm_lm, cudaFuncAttributeMaxDynamicSharedMemorySize,
                         (int)G_SMEM_BYTES);
    cudaFuncSetAttribute(attn_kernel, cudaFuncAttributeMaxDynamicSharedMemorySize,
                         (int)ATTN_SMEM_BYTES);

    {
        int n4 = BS * D_MODEL / 4;
        round_copy4<<<(n4 + 255) / 256, 256>>>(x, x_p, n4);
        transpose_round<<<dim3(QKV_N / 32, D_MODEL / 32), dim3(32, 8)>>>(Wqkv, wqkvT_p, D_MODEL, QKV_N);
        transpose_round<<<dim3(D_MODEL / 32, D_MODEL / 32), dim3(32, 8)>>>(Wout, woutT_p, D_MODEL, D_MODEL);
    }

    gemm_lm<<<dim3(QKV_N / 128, BS / 128), 512, G_SMEM_BYTES>>>(
        x_p, wqkvT_p, bqkv, qkv_p, BS, QKV_N, D_MODEL, 1);

    attn_kernel<<<dim3(SEQ / 128, N_HEADS, BATCH), 256, ATTN_SMEM_BYTES>>>(qkv_p, att_p);

    gemm_lm<<<dim3(D_MODEL / 128, BS / 128), 512, G_SMEM_BYTES>>>(
        att_p, woutT_p, bout, out, BS, D_MODEL, D_MODEL, 0);
}

// round 7
// speedup vs baseline: 1.0132x; 1.0132x over previous
#include <cuda_runtime.h>
#include <cstdint>

#define D_MODEL 2048
#define N_HEADS 16
#define D_HEAD  128
#define SEQ     2048
#define BATCH   2
#define BS      (BATCH * SEQ)      // 4096
#define QKV_N   (3 * D_MODEL)      // 6144

// Scratch (allocation-free rule: __device__ globals)
__device__ float g_qkv[(size_t)BS * QKV_N];          // 96 MB (tf32, rounded)
__device__ float g_att[(size_t)BS * D_MODEL];        // 32 MB (tf32, rounded)
__device__ float g_x[(size_t)BS * D_MODEL];          // 32 MB (tf32-rounded x)
__device__ float g_wqkvT[(size_t)QKV_N * D_MODEL];   // 48 MB (W_qkv^T, rounded)
__device__ float g_woutT[(size_t)D_MODEL * D_MODEL]; // 16 MB (W_out^T, rounded)

__device__ __forceinline__ float tf32r(float x) {
    asm("cvt.rna.tf32.f32 %0, %1;" : "=f"(x) : "f"(x));
    return x;
}

__device__ __forceinline__ uint32_t smem_u32(const void* p) {
    uint32_t a;
    asm("{ .reg .u64 t; cvta.to.shared.u64 t, %1; cvt.u32.u64 %0, t; }" : "=r"(a) : "l"(p));
    return a;
}

__device__ __forceinline__ void mma8(float d[4], const uint32_t a[4], const uint32_t b[2]) {
    asm volatile(
        "mma.sync.aligned.m16n8k8.row.col.f32.tf32.tf32.f32 "
        "{%0,%1,%2,%3}, {%4,%5,%6,%7}, {%8,%9}, {%0,%1,%2,%3};\n"
        : "+f"(d[0]), "+f"(d[1]), "+f"(d[2]), "+f"(d[3])
        : "r"(a[0]), "r"(a[1]), "r"(a[2]), "r"(a[3]), "r"(b[0]), "r"(b[1]));
}

#define LDSM4(R0, R1, R2, R3, ADDR) \
    asm volatile("ldmatrix.sync.aligned.m8n8.x4.shared.b16 {%0,%1,%2,%3}, [%4];" \
                 : "=r"(R0), "=r"(R1), "=r"(R2), "=r"(R3) : "r"(ADDR))

__device__ __forceinline__ void cpasync16(uint32_t dst, const void* src) {
    asm volatile("cp.async.cg.shared.global [%0], [%1], 16;" :: "r"(dst), "l"(src) : "memory");
}
__device__ __forceinline__ void cp_commit() {
    asm volatile("cp.async.commit_group;" ::: "memory");
}
__device__ __forceinline__ void cp_wait0() {
    asm volatile("cp.async.wait_group 0;" ::: "memory");
}
__device__ __forceinline__ void cp_wait1() {
    asm volatile("cp.async.wait_group 1;" ::: "memory");
}

// ============================================================================
// Prep kernels
// ============================================================================
__global__ void round_copy4(const float* __restrict__ in, float* __restrict__ out, int n4) {
    int i = blockIdx.x * blockDim.x + threadIdx.x;
    if (i < n4) {
        float4 v = ((const float4*)in)[i];
        v.x = tf32r(v.x); v.y = tf32r(v.y); v.z = tf32r(v.z); v.w = tf32r(v.w);
        ((float4*)out)[i] = v;
    }
}

__global__ void transpose_round(const float* __restrict__ W, float* __restrict__ Wt,
                                int K, int N) {
    __shared__ float t[32][33];
    int n0 = blockIdx.x * 32, k0 = blockIdx.y * 32;
    int tx = threadIdx.x, ty = threadIdx.y;
#pragma unroll
    for (int i = ty; i < 32; i += 8)
        t[i][tx] = tf32r(W[(size_t)(k0 + i) * N + n0 + tx]);
    __syncthreads();
#pragma unroll
    for (int i = ty; i < 32; i += 8)
        Wt[(size_t)(n0 + i) * K + k0 + tx] = t[tx][i];
}

// ============================================================================
// tf32 GEMM: CTA tile 128(M) x 256(N) x 32(K), 8 warps (2x4), warp tile 64x64.
// 3-stage cp.async ring, one __syncthreads per slab.
// Fragment-traffic-per-flop minimized (crossbar was the R5/R6 co-limiter).
// ============================================================================
#define G_ASZ (128 * 36)                       // A tile floats
#define G_BSZ (256 * 36)                       // B tile floats
#define G_STAGE_BYTES ((G_ASZ + G_BSZ) * 4u)   // 55296
#define G_SMEM_BYTES (3u * G_STAGE_BYTES)      // 165888

__global__ __launch_bounds__(256, 1) void gemm_lm(
    const float* __restrict__ A, const float* __restrict__ Bt,
    const float* __restrict__ bias, float* __restrict__ C,
    int M, int N, int K, int round_out)
{
    extern __shared__ float smem[];
    const uint32_t sbase = smem_u32(smem);

    const int tid  = threadIdx.x;
    const int lane = tid & 31;
    const int wid  = tid >> 5;        // 0..7
    const int wm   = wid >> 2;        // 0..1 (64-row slice)
    const int wn   = wid & 3;         // 0..3 (64-col slice)
    const int g    = lane >> 2;
    const int tig  = lane & 3;

    const int m0 = blockIdx.y * 128;
    const int n0 = blockIdx.x * 256;
    const float* Ag = A + (size_t)m0 * K;
    const float* Bg = Bt + (size_t)n0 * K;
    const int nslab = K >> 5;

    // cp.async mapping: A 4 chunks, B 8 chunks of 16B per thread
    const int crow = tid >> 3;        // 0..31
    const int ccj  = (tid & 7) * 4;   // float col within 32

    const int lmrow = lane & 15;
    const int lmc4  = (lane >> 4) * 4;
    const uint32_t a_lm = sbase + (((wm * 64 + lmrow) * 36 + lmc4) << 2);
    const uint32_t b_lm = sbase + (uint32_t)(G_ASZ * 4) + (((wn * 64 + lmrow) * 36 + lmc4) << 2);

    float acc[4][8][4];
#pragma unroll
    for (int mt = 0; mt < 4; mt++)
#pragma unroll
        for (int nt = 0; nt < 8; nt++)
#pragma unroll
            for (int i = 0; i < 4; i++) acc[mt][nt][i] = 0.f;

    auto load_slab = [&](int i, int s) {
        const uint32_t ab = sbase + (uint32_t)s * G_STAGE_BYTES;
        const uint32_t bb = ab + (uint32_t)(G_ASZ * 4);
        const int k0 = i << 5;
#pragma unroll
        for (int r = 0; r < 4; r++) {
            int row = crow + r * 32;
            cpasync16(ab + ((row * 36 + ccj) << 2), Ag + (size_t)row * K + k0 + ccj);
        }
#pragma unroll
        for (int r = 0; r < 8; r++) {
            int row = crow + r * 32;
            cpasync16(bb + ((row * 36 + ccj) << 2), Bg + (size_t)row * K + k0 + ccj);
        }
        cp_commit();
    };

    load_slab(0, 0);
    load_slab(1, 1);

    int s_c = 0;
    int s_l = 2;
    for (int i = 0; i < nslab; i++) {
        cp_wait1();
        __syncthreads();
        if (i + 2 < nslab) load_slab(i + 2, s_l);
        else cp_commit();

        const uint32_t a_st = a_lm + (uint32_t)s_c * G_STAGE_BYTES;
        const uint32_t b_st = b_lm + (uint32_t)s_c * G_STAGE_BYTES;
#pragma unroll
        for (int ks = 0; ks < 4; ks++) {
            const uint32_t ka = a_st + ks * 32;
            uint32_t af[4][4];
#pragma unroll
            for (int mt = 0; mt < 4; mt++)
                LDSM4(af[mt][0], af[mt][1], af[mt][2], af[mt][3], ka + mt * 2304);
            const uint32_t kb = b_st + ks * 32;
#pragma unroll
            for (int q = 0; q < 4; q++) {
                uint32_t b0, b1, b2, b3;
                LDSM4(b0, b1, b2, b3, kb + q * 2304);
                uint32_t bfA[2] = { b0, b2 };
                uint32_t bfB[2] = { b1, b3 };
#pragma unroll
                for (int mt = 0; mt < 4; mt++) {
                    mma8(acc[mt][2 * q],     af[mt], bfA);
                    mma8(acc[mt][2 * q + 1], af[mt], bfB);
                }
            }
        }
        s_c++; if (s_c == 3) s_c = 0;
        s_l++; if (s_l == 3) s_l = 0;
    }

#pragma unroll
    for (int mt = 0; mt < 4; mt++) {
        int r = m0 + wm * 64 + mt * 16 + g;
#pragma unroll
        for (int nt = 0; nt < 8; nt++) {
            int c = n0 + wn * 64 + nt * 8 + tig * 2;
            float b0 = bias[c], b1 = bias[c + 1];
            float v0 = acc[mt][nt][0] + b0;
            float v1 = acc[mt][nt][1] + b1;
            float v2 = acc[mt][nt][2] + b0;
            float v3 = acc[mt][nt][3] + b1;
            if (round_out) { v0 = tf32r(v0); v1 = tf32r(v1); v2 = tf32r(v2); v3 = tf32r(v3); }
            *(float2*)(C + (size_t)r * N + c)       = make_float2(v0, v1);
            *(float2*)(C + (size_t)(r + 8) * N + c) = make_float2(v2, v3);
        }
    }
}

// ============================================================================
// Flash attention (causal): cp.async Q + double-buffered K, register-pipelined V.
// (unchanged from R5)
// ============================================================================
#define LDQ 132
#define LDV 68
#define ATTN_SMEM_FLOATS (128 * LDQ + 2 * 64 * LDQ + 128 * LDV + 128 * LDV)
#define ATTN_SMEM_BYTES (ATTN_SMEM_FLOATS * 4)

__global__ __launch_bounds__(256) void attn_kernel(
    const float* __restrict__ qkv, float* __restrict__ out)
{
    extern __shared__ float sm[];
    float* Vst = sm + 128 * LDQ + 2 * 64 * LDQ;
    float* Ps  = Vst + 128 * LDV;

    const int tid  = threadIdx.x;
    const int lane = tid & 31;
    const int wid  = tid >> 5;
    const int g    = lane >> 2;
    const int tig  = lane & 3;
    const int rbase = wid * 16;
    const int r1 = rbase + g;
    const int r2 = r1 + 8;

    const int qt = blockIdx.x;
    const int h  = blockIdx.y;
    const int b  = blockIdx.z;
    const int q0 = qt * 128;

    const float scale = 0.08838834764831845f; // 1/sqrt(128)
    const float* Qg = qkv + (size_t)b * SEQ * QKV_N + h * D_HEAD;
    const float* Kg = Qg + D_MODEL;
    const float* Vg = Qg + 2 * D_MODEL;

    const int lmrow = lane & 15;
    const int lmc4  = (lane >> 4) * 4;
    const uint32_t sb = smem_u32(sm);
    const uint32_t q_lm  = sb + (((rbase + lmrow) * LDQ + lmc4) << 2);
    const uint32_t k_lm0 = sb + ((128 * LDQ + lmrow * LDQ + lmc4) << 2);
    const uint32_t v_lm  = sb + (((128 + 128) * LDQ + lmrow * LDV + lmc4) << 2);
    const uint32_t p_lm  = sb + (((128 + 128) * LDQ + 128 * LDV + (rbase + lmrow) * LDV + lmc4) << 2);

    const int vn  = tid & 127;
    const int vk4 = tid >> 7;

    auto load_q = [&]() {
        for (int i = tid; i < 128 * 32; i += 256) {
            int r = i >> 5;
            int c = (i & 31) * 4;
            cpasync16(sb + ((r * LDQ + c) << 2), Qg + (size_t)(q0 + r) * QKV_N + c);
        }
    };
    auto load_k = [&](int j, int buf) {
        const int kb = j * 64;
        const uint32_t kbase = sb + ((128 * LDQ + buf * 64 * LDQ) << 2);
        for (int i = tid; i < 64 * 32; i += 256) {
            int r = i >> 5;
            int c = (i & 31) * 4;
            cpasync16(kbase + ((r * LDQ + c) << 2), Kg + (size_t)(kb + r) * QKV_N + c);
        }
    };

    load_q();
    load_k(0, 0);
    cp_commit();

    float o[16][4];
#pragma unroll
    for (int nt = 0; nt < 16; nt++)
#pragma unroll
        for (int i = 0; i < 4; i++) o[nt][i] = 0.f;
    float m1 = -1e30f, m2 = -1e30f, l1 = 0.f, l2 = 0.f;

    const int njt = 2 * qt + 2;

    float4 vr[8];
#pragma unroll
    for (int t = 0; t < 8; t++) {
        int k4 = vk4 + t * 2;
        vr[t].x = Vg[(size_t)(k4 * 4 + 0) * QKV_N + vn];
        vr[t].y = Vg[(size_t)(k4 * 4 + 1) * QKV_N + vn];
        vr[t].z = Vg[(size_t)(k4 * 4 + 2) * QKV_N + vn];
        vr[t].w = Vg[(size_t)(k4 * 4 + 3) * QKV_N + vn];
    }

    for (int j = 0; j < njt; j++) {
        cp_wait0();
        __syncthreads();

#pragma unroll
        for (int t = 0; t < 8; t++)
            *(float4*)(Vst + vn * LDV + (vk4 + t * 2) * 4) = vr[t];

        if (j + 1 < njt) load_k(j + 1, (j + 1) & 1);
        cp_commit();
        __syncthreads();

        if (j + 1 < njt) {
            const float* Vt = Vg + (size_t)(j + 1) * 64 * QKV_N;
#pragma unroll
            for (int t = 0; t < 8; t++) {
                int k4 = vk4 + t * 2;
                vr[t].x = Vt[(size_t)(k4 * 4 + 0) * QKV_N + vn];
                vr[t].y = Vt[(size_t)(k4 * 4 + 1) * QKV_N + vn];
                vr[t].z = Vt[(size_t)(k4 * 4 + 2) * QKV_N + vn];
                vr[t].w = Vt[(size_t)(k4 * 4 + 3) * QKV_N + vn];
            }
        }

        const uint32_t k_lm = k_lm0 + ((j & 1) ? (uint32_t)(64 * LDQ * 4) : 0u);
        float s[8][4];
#pragma unroll
        for (int nt = 0; nt < 8; nt++)
#pragma unroll
            for (int i = 0; i < 4; i++) s[nt][i] = 0.f;

#pragma unroll
        for (int ks = 0; ks < 16; ks++) {
            uint32_t af[4];
            LDSM4(af[0], af[1], af[2], af[3], q_lm + ks * 32);
            const uint32_t kbb = k_lm + ks * 32;
#pragma unroll
            for (int q = 0; q < 4; q++) {
                uint32_t b0, b1, b2, b3;
                LDSM4(b0, b1, b2, b3, kbb + q * (16 * LDQ * 4));
                uint32_t bfA[2] = { b0, b2 };
                uint32_t bfB[2] = { b1, b3 };
                mma8(s[2 * q],     af, bfA);
                mma8(s[2 * q + 1], af, bfB);
            }
        }

#pragma unroll
        for (int nt = 0; nt < 8; nt++) {
            s[nt][0] *= scale; s[nt][1] *= scale;
            s[nt][2] *= scale; s[nt][3] *= scale;
        }

        if (j >= 2 * qt) {
            const int koff = (j - 2 * qt) << 6;
            const int lim1 = r1 - koff;
            const int lim2 = r2 - koff;
#pragma unroll
            for (int nt = 0; nt < 8; nt++) {
                int c0 = nt * 8 + tig * 2;
                if (c0     > lim1) s[nt][0] = -1e30f;
                if (c0 + 1 > lim1) s[nt][1] = -1e30f;
                if (c0     > lim2) s[nt][2] = -1e30f;
                if (c0 + 1 > lim2) s[nt][3] = -1e30f;
            }
        }

        float mx1 = -1e30f, mx2 = -1e30f;
#pragma unroll
        for (int nt = 0; nt < 8; nt++) {
            mx1 = fmaxf(mx1, fmaxf(s[nt][0], s[nt][1]));
            mx2 = fmaxf(mx2, fmaxf(s[nt][2], s[nt][3]));
        }
        mx1 = fmaxf(mx1, __shfl_xor_sync(0xffffffffu, mx1, 1));
        mx1 = fmaxf(mx1, __shfl_xor_sync(0xffffffffu, mx1, 2));
        mx2 = fmaxf(mx2, __shfl_xor_sync(0xffffffffu, mx2, 1));
        mx2 = fmaxf(mx2, __shfl_xor_sync(0xffffffffu, mx2, 2));

        const float mn1 = fmaxf(m1, mx1);
        const float mn2 = fmaxf(m2, mx2);
        const float al1 = __expf(m1 - mn1);
        const float al2 = __expf(m2 - mn2);

        float sm1 = 0.f, sm2 = 0.f;
#pragma unroll
        for (int nt = 0; nt < 8; nt++) {
            s[nt][0] = __expf(s[nt][0] - mn1);
            s[nt][1] = __expf(s[nt][1] - mn1);
            s[nt][2] = __expf(s[nt][2] - mn2);
            s[nt][3] = __expf(s[nt][3] - mn2);
            sm1 += s[nt][0] + s[nt][1];
            sm2 += s[nt][2] + s[nt][3];
        }
        sm1 += __shfl_xor_sync(0xffffffffu, sm1, 1);
        sm1 += __shfl_xor_sync(0xffffffffu, sm1, 2);
        sm2 += __shfl_xor_sync(0xffffffffu, sm2, 1);
        sm2 += __shfl_xor_sync(0xffffffffu, sm2, 2);

        l1 = al1 * l1 + sm1;
        l2 = al2 * l2 + sm2;
        m1 = mn1;
        m2 = mn2;

#pragma unroll
        for (int nt = 0; nt < 16; nt++) {
            o[nt][0] *= al1; o[nt][1] *= al1;
            o[nt][2] *= al2; o[nt][3] *= al2;
        }

#pragma unroll
        for (int nt = 0; nt < 8; nt++) {
            int c = nt * 8 + tig * 2;
            *(float2*)(Ps + r1 * LDV + c) = make_float2(tf32r(s[nt][0]), tf32r(s[nt][1]));
            *(float2*)(Ps + r2 * LDV + c) = make_float2(tf32r(s[nt][2]), tf32r(s[nt][3]));
        }
        __syncwarp();

#pragma unroll
        for (int ks = 0; ks < 8; ks++) {
            uint32_t af[4];
            LDSM4(af[0], af[1], af[2], af[3], p_lm + ks * 32);
            const uint32_t vb = v_lm + ks * 32;
#pragma unroll
            for (int q = 0; q < 8; q++) {
                uint32_t b0, b1, b2, b3;
                LDSM4(b0, b1, b2, b3, vb + q * (16 * LDV * 4));
                uint32_t bfA[2] = { b0, b2 };
                uint32_t bfB[2] = { b1, b3 };
                mma8(o[2 * q],     af, bfA);
                mma8(o[2 * q + 1], af, bfB);
            }
        }
        __syncwarp();
    }

    const float inv1 = 1.f / l1;
    const float inv2 = 1.f / l2;
    float* Og = out + ((size_t)b * SEQ + q0) * D_MODEL + h * D_HEAD;
#pragma unroll
    for (int nt = 0; nt < 16; nt++) {
        int c = nt * 8 + tig * 2;
        *(float2*)(Og + (size_t)r1 * D_MODEL + c) =
            make_float2(tf32r(o[nt][0] * inv1), tf32r(o[nt][1] * inv1));
        *(float2*)(Og + (size_t)r2 * D_MODEL + c) =
            make_float2(tf32r(o[nt][2] * inv2), tf32r(o[nt][3] * inv2));
    }
}

// ============================================================================
// Launch
// ============================================================================
extern "C" void kernel_launch(void* const* d_in, const int* in_sizes, int n_in,
                              void* d_out, int out_size) {
    const float* x    = (const float*)d_in[0];
    const float* Wqkv = (const float*)d_in[1];
    const float* bqkv = (const float*)d_in[2];
    const float* Wout = (const float*)d_in[3];
    const float* bout = (const float*)d_in[4];
    float* out = (float*)d_out;

    float *qkv_p, *att_p, *x_p, *wqkvT_p, *woutT_p;
    cudaGetSymbolAddress((void**)&qkv_p, g_qkv);
    cudaGetSymbolAddress((void**)&att_p, g_att);
    cudaGetSymbolAddress((void**)&x_p, g_x);
    cudaGetSymbolAddress((void**)&wqkvT_p, g_wqkvT);
    cudaGetSymbolAddress((void**)&woutT_p, g_woutT);

    cudaFuncSetAttribute(gemm_lm, cudaFuncAttributeMaxDynamicSharedMemorySize,
                         (int)G_SMEM_BYTES);
    cudaFuncSetAttribute(attn_kernel, cudaFuncAttributeMaxDynamicSharedMemorySize,
                         (int)ATTN_SMEM_BYTES);

    {
        int n4 = BS * D_MODEL / 4;
        round_copy4<<<(n4 + 255) / 256, 256>>>(x, x_p, n4);
        transpose_round<<<dim3(QKV_N / 32, D_MODEL / 32), dim3(32, 8)>>>(Wqkv, wqkvT_p, D_MODEL, QKV_N);
        transpose_round<<<dim3(D_MODEL / 32, D_MODEL / 32), dim3(32, 8)>>>(Wout, woutT_p, D_MODEL, D_MODEL);
    }

    // 1) qkv = x @ W_qkv + b_qkv   [4096, 6144], output tf32-rounded
    gemm_lm<<<dim3(QKV_N / 256, BS / 128), 256, G_SMEM_BYTES>>>(
        x_p, wqkvT_p, bqkv, qkv_p, BS, QKV_N, D_MODEL, 1);

    // 2) causal flash attention -> g_att (tf32-rounded)
    attn_kernel<<<dim3(SEQ / 128, N_HEADS, BATCH), 256, ATTN_SMEM_BYTES>>>(qkv_p, att_p);

    // 3) out = att @ W_out + b_out  [4096, 2048]
    gemm_lm<<<dim3(D_MODEL / 256, BS / 128), 256, G_SMEM_BYTES>>>(
        att_p, woutT_p, bout, out, BS, D_MODEL, D_MODEL, 0);
}

// round 8
// speedup vs baseline: 1.9806x; 1.9548x over previous
#include <cuda_runtime.h>
#include <cuda_fp16.h>
#include <cstdint>

#define D_MODEL 2048
#define N_HEADS 16
#define D_HEAD  128
#define SEQ     2048
#define BATCH   2
#define BS      (BATCH * SEQ)      // 4096
#define QKV_N   (3 * D_MODEL)      // 6144

// Scratch (allocation-free rule: __device__ globals) — all fp16 now
__device__ __half g_qkv[(size_t)BS * QKV_N];          // 48 MB
__device__ __half g_att[(size_t)BS * D_MODEL];        // 16 MB
__device__ __half g_xh[(size_t)BS * D_MODEL];         // 16 MB
__device__ __half g_wqkvT[(size_t)QKV_N * D_MODEL];   // 24 MB
__device__ __half g_woutT[(size_t)D_MODEL * D_MODEL]; // 8 MB

__device__ __forceinline__ uint32_t smem_u32(const void* p) {
    uint32_t a;
    asm("{ .reg .u64 t; cvta.to.shared.u64 t, %1; cvt.u32.u64 %0, t; }" : "=r"(a) : "l"(p));
    return a;
}

// fp16 mma, fp32 accumulate: D(16x8) += A(16x16) x B(16x8)
__device__ __forceinline__ void mma16(float d[4], const uint32_t a[4], const uint32_t b[2]) {
    asm volatile(
        "mma.sync.aligned.m16n8k16.row.col.f32.f16.f16.f32 "
        "{%0,%1,%2,%3}, {%4,%5,%6,%7}, {%8,%9}, {%0,%1,%2,%3};\n"
        : "+f"(d[0]), "+f"(d[1]), "+f"(d[2]), "+f"(d[3])
        : "r"(a[0]), "r"(a[1]), "r"(a[2]), "r"(a[3]), "r"(b[0]), "r"(b[1]));
}

#define LDSM4(R0, R1, R2, R3, ADDR) \
    asm volatile("ldmatrix.sync.aligned.m8n8.x4.shared.b16 {%0,%1,%2,%3}, [%4];" \
                 : "=r"(R0), "=r"(R1), "=r"(R2), "=r"(R3) : "r"(ADDR))

__device__ __forceinline__ void cpasync16(uint32_t dst, const void* src) {
    asm volatile("cp.async.cg.shared.global [%0], [%1], 16;" :: "r"(dst), "l"(src) : "memory");
}
__device__ __forceinline__ void cp_commit() {
    asm volatile("cp.async.commit_group;" ::: "memory");
}
__device__ __forceinline__ void cp_wait0() {
    asm volatile("cp.async.wait_group 0;" ::: "memory");
}
__device__ __forceinline__ void cp_wait1() {
    asm volatile("cp.async.wait_group 1;" ::: "memory");
}

// ============================================================================
// Prep kernels: fp32 -> fp16 convert, and transpose-convert for weights.
// ============================================================================
__global__ void conv_half(const float* __restrict__ in, __half* __restrict__ out, int n4) {
    int i = blockIdx.x * blockDim.x + threadIdx.x;
    if (i < n4) {
        float4 v = ((const float4*)in)[i];
        __half2* o = (__half2*)(out) + i * 2;
        o[0] = __floats2half2_rn(v.x, v.y);
        o[1] = __floats2half2_rn(v.z, v.w);
    }
}

// W [K][N] fp32 -> Wt [N][K] fp16
__global__ void transpose_half(const float* __restrict__ W, __half* __restrict__ Wt,
                               int K, int N) {
    __shared__ float t[32][33];
    int n0 = blockIdx.x * 32, k0 = blockIdx.y * 32;
    int tx = threadIdx.x, ty = threadIdx.y;
#pragma unroll
    for (int i = ty; i < 32; i += 8)
        t[i][tx] = W[(size_t)(k0 + i) * N + n0 + tx];
    __syncthreads();
#pragma unroll
    for (int i = ty; i < 32; i += 8)
        Wt[(size_t)(n0 + i) * K + k0 + tx] = __float2half(t[tx][i]);
}

// ============================================================================
// fp16 GEMM: C[M,N] = A[M,K] @ Bt[N,K]^T + bias[N]
// Block 128x128, 8 warps (4x2), warp tile 32x64, K-slab 64 halfs.
// Row stride 72 halfs = 144 B (ldmatrix 16B-group conflict-free).
// 3-stage cp.async ring. store_half: C as fp16 (Ch) else fp32 (Cf).
// ============================================================================
#define G_LDS 72
#define G_TILE_BYTES (128 * G_LDS * 2)              // 18432 per operand
#define G_STAGE_BYTES (2u * G_TILE_BYTES)           // 36864
#define G_SMEM_BYTES (3u * G_STAGE_BYTES)           // 110592

__global__ __launch_bounds__(256, 2) void gemm_h(
    const __half* __restrict__ A, const __half* __restrict__ Bt,
    const float* __restrict__ bias, float* __restrict__ Cf, __half* __restrict__ Ch,
    int M, int N, int K, int store_half)
{
    extern __shared__ __half smem[];
    const uint32_t sbase = smem_u32(smem);

    const int tid  = threadIdx.x;
    const int lane = tid & 31;
    const int wid  = tid >> 5;
    const int wm   = wid >> 1;   // 0..3 (32-row slice)
    const int wn   = wid & 1;    // 0..1 (64-col slice)
    const int g    = lane >> 2;
    const int tig  = lane & 3;

    const int m0 = blockIdx.y * 128;
    const int n0 = blockIdx.x * 128;
    const __half* Ag = A + (size_t)m0 * K;
    const __half* Bg = Bt + (size_t)n0 * K;
    const int nslab = K >> 6;    // 64 halfs per slab

    // cp.async: per thread 4 chunks (16B = 8 halfs) per operand
    const int crow = tid >> 3;        // 0..31
    const int ccj  = (tid & 7) * 8;   // half col within 64

    const int lmrow = lane & 15;
    const uint32_t lmc16 = (lane >> 4) * 16;   // byte col (0 or 16)
    const uint32_t a_lm = sbase + (wm * 32 + lmrow) * 144 + lmc16;
    const uint32_t b_lm = sbase + (uint32_t)G_TILE_BYTES + (wn * 64 + lmrow) * 144 + lmc16;

    float acc[2][8][4];
#pragma unroll
    for (int mt = 0; mt < 2; mt++)
#pragma unroll
        for (int nt = 0; nt < 8; nt++)
#pragma unroll
            for (int i = 0; i < 4; i++) acc[mt][nt][i] = 0.f;

    auto load_slab = [&](int i, int s) {
        const uint32_t ab = sbase + (uint32_t)s * G_STAGE_BYTES;
        const uint32_t bb = ab + (uint32_t)G_TILE_BYTES;
        const int k0 = i << 6;
#pragma unroll
        for (int r = 0; r < 4; r++) {
            int row = crow + r * 32;
            cpasync16(ab + row * 144 + ccj * 2, Ag + (size_t)row * K + k0 + ccj);
        }
#pragma unroll
        for (int r = 0; r < 4; r++) {
            int row = crow + r * 32;
            cpasync16(bb + row * 144 + ccj * 2, Bg + (size_t)row * K + k0 + ccj);
        }
        cp_commit();
    };

    load_slab(0, 0);
    load_slab(1, 1);

    int s_c = 0;
    int s_l = 2;
    for (int i = 0; i < nslab; i++) {
        cp_wait1();
        __syncthreads();
        if (i + 2 < nslab) load_slab(i + 2, s_l);
        else cp_commit();

        const uint32_t a_st = a_lm + (uint32_t)s_c * G_STAGE_BYTES;
        const uint32_t b_st = b_lm + (uint32_t)s_c * G_STAGE_BYTES;
#pragma unroll
        for (int ks = 0; ks < 4; ks++) {     // 4 x k16 = 64
            const uint32_t ka = a_st + ks * 32;
            uint32_t af0[4], af1[4];
            LDSM4(af0[0], af0[1], af0[2], af0[3], ka);
            LDSM4(af1[0], af1[1], af1[2], af1[3], ka + 2304);  // +16 rows
            const uint32_t kb = b_st + ks * 32;
#pragma unroll
            for (int q = 0; q < 4; q++) {
                uint32_t b0, b1, b2, b3;
                LDSM4(b0, b1, b2, b3, kb + q * 2304);
                uint32_t bfA[2] = { b0, b2 };
                uint32_t bfB[2] = { b1, b3 };
                mma16(acc[0][2 * q],     af0, bfA);
                mma16(acc[0][2 * q + 1], af0, bfB);
                mma16(acc[1][2 * q],     af1, bfA);
                mma16(acc[1][2 * q + 1], af1, bfB);
            }
        }
        s_c++; if (s_c == 3) s_c = 0;
        s_l++; if (s_l == 3) s_l = 0;
    }

#pragma unroll
    for (int mt = 0; mt < 2; mt++) {
        int r = m0 + wm * 32 + mt * 16 + g;
#pragma unroll
        for (int nt = 0; nt < 8; nt++) {
            int c = n0 + wn * 64 + nt * 8 + tig * 2;
            float b0 = bias[c], b1 = bias[c + 1];
            float v0 = acc[mt][nt][0] + b0;
            float v1 = acc[mt][nt][1] + b1;
            float v2 = acc[mt][nt][2] + b0;
            float v3 = acc[mt][nt][3] + b1;
            if (store_half) {
                *(__half2*)(Ch + (size_t)r * N + c)       = __floats2half2_rn(v0, v1);
                *(__half2*)(Ch + (size_t)(r + 8) * N + c) = __floats2half2_rn(v2, v3);
            } else {
                *(float2*)(Cf + (size_t)r * N + c)       = make_float2(v0, v1);
                *(float2*)(Cf + (size_t)(r + 8) * N + c) = make_float2(v2, v3);
            }
        }
    }
}

// ============================================================================
// Flash attention (causal), fp16 mma: warp-owns-rows, cp.async Q + double-
// buffered K, register-pipelined V. Softmax fp32. BLOCK_M=128, BLOCK_N=64.
// ============================================================================
#define LDQ 136   // halfs (272 B rows; 272/16=17 -> conflict-free ldmatrix)
#define LDV 72    // halfs (144 B rows)
#define ATTN_SMEM_BYTES ((256 * LDQ + 128 * LDV + 128 * LDV) * 2)

__global__ __launch_bounds__(256) void attn_kernel(
    const __half* __restrict__ qkv, __half* __restrict__ out)
{
    extern __shared__ __half smh[];
    __half* Vst = smh + 256 * LDQ;          // [128][72] (row=d, col=kv)
    __half* Ps  = Vst + 128 * LDV;          // [128][72]

    const int tid  = threadIdx.x;
    const int lane = tid & 31;
    const int wid  = tid >> 5;
    const int g    = lane >> 2;
    const int tig  = lane & 3;
    const int rbase = wid * 16;
    const int r1 = rbase + g;
    const int r2 = r1 + 8;

    const int qt = blockIdx.x;
    const int h  = blockIdx.y;
    const int b  = blockIdx.z;
    const int q0 = qt * 128;

    const float scale = 0.08838834764831845f; // 1/sqrt(128)
    const __half* Qg = qkv + (size_t)b * SEQ * QKV_N + h * D_HEAD;
    const __half* Kg = Qg + D_MODEL;
    const __half* Vg = Qg + 2 * D_MODEL;

    const int lmrow = lane & 15;
    const uint32_t lmc16 = (lane >> 4) * 16;
    const uint32_t sb = smem_u32(smh);
    const uint32_t q_lm  = sb + (rbase + lmrow) * 272 + lmc16;
    const uint32_t k_lm0 = sb + 128 * 272 + lmrow * 272 + lmc16;
    const uint32_t v_lm  = sb + 256 * 272 + lmrow * 144 + lmc16;
    const uint32_t p_lm  = sb + 256 * 272 + 128 * 144 + (rbase + lmrow) * 144 + lmc16;

    const int vn  = tid & 127;   // d index
    const int vk4 = tid >> 7;    // 0/1

    auto load_q = [&]() {
        for (int i = tid; i < 128 * 16; i += 256) {     // 16 chunks of 16B per row
            int r = i >> 4;
            int c = (i & 15) * 8;                        // half col
            cpasync16(sb + r * 272 + c * 2, Qg + (size_t)(q0 + r) * QKV_N + c);
        }
    };
    auto load_k = [&](int j, int buf) {
        const int kb = j * 64;
        const uint32_t kbase = sb + 128 * 272 + buf * 64 * 272;
        for (int i = tid; i < 64 * 16; i += 256) {
            int r = i >> 4;
            int c = (i & 15) * 8;
            cpasync16(kbase + r * 272 + c * 2, Kg + (size_t)(kb + r) * QKV_N + c);
        }
    };

    load_q();
    load_k(0, 0);
    cp_commit();

    float o[16][4];
#pragma unroll
    for (int nt = 0; nt < 16; nt++)
#pragma unroll
        for (int i = 0; i < 4; i++) o[nt][i] = 0.f;
    float m1 = -1e30f, m2 = -1e30f, l1 = 0.f, l2 = 0.f;

    const int njt = 2 * qt + 2;

    // V tile prefetch: each thread owns d=vn, kv = (vk4+2t)*4 .. +3 for t 0..7
    __half vr[32];
#pragma unroll
    for (int t = 0; t < 8; t++) {
        int kv = (vk4 + 2 * t) * 4;
#pragma unroll
        for (int u = 0; u < 4; u++)
            vr[t * 4 + u] = Vg[(size_t)(kv + u) * QKV_N + vn];
    }

    for (int j = 0; j < njt; j++) {
        cp_wait0();
        __syncthreads();

        // store V[j] (transposed) from registers
#pragma unroll
        for (int t = 0; t < 8; t++) {
            int kv = (vk4 + 2 * t) * 4;
            *(__half2*)(Vst + vn * LDV + kv)     = __halves2half2(vr[t * 4 + 0], vr[t * 4 + 1]);
            *(__half2*)(Vst + vn * LDV + kv + 2) = __halves2half2(vr[t * 4 + 2], vr[t * 4 + 3]);
        }

        if (j + 1 < njt) load_k(j + 1, (j + 1) & 1);
        cp_commit();
        __syncthreads();

        // prefetch V[j+1]
        if (j + 1 < njt) {
            const __half* Vt = Vg + (size_t)(j + 1) * 64 * QKV_N;
#pragma unroll
            for (int t = 0; t < 8; t++) {
                int kv = (vk4 + 2 * t) * 4;
#pragma unroll
                for (int u = 0; u < 4; u++)
                    vr[t * 4 + u] = Vt[(size_t)(kv + u) * QKV_N + vn];
            }
        }

        // ---- S = Q @ K^T : warp 16 x 64, d = 128 (8 x k16) ----
        const uint32_t k_lm = k_lm0 + ((j & 1) ? (uint32_t)(64 * 272) : 0u);
        float s[8][4];
#pragma unroll
        for (int nt = 0; nt < 8; nt++)
#pragma unroll
            for (int i = 0; i < 4; i++) s[nt][i] = 0.f;

#pragma unroll
        for (int ks = 0; ks < 8; ks++) {
            uint32_t af[4];
            LDSM4(af[0], af[1], af[2], af[3], q_lm + ks * 32);
            const uint32_t kbb = k_lm + ks * 32;
#pragma unroll
            for (int q = 0; q < 4; q++) {
                uint32_t b0, b1, b2, b3;
                LDSM4(b0, b1, b2, b3, kbb + q * (16 * 272));
                uint32_t bfA[2] = { b0, b2 };
                uint32_t bfB[2] = { b1, b3 };
                mma16(s[2 * q],     af, bfA);
                mma16(s[2 * q + 1], af, bfB);
            }
        }

#pragma unroll
        for (int nt = 0; nt < 8; nt++) {
            s[nt][0] *= scale; s[nt][1] *= scale;
            s[nt][2] *= scale; s[nt][3] *= scale;
        }

        if (j >= 2 * qt) {
            const int koff = (j - 2 * qt) << 6;
            const int lim1 = r1 - koff;
            const int lim2 = r2 - koff;
#pragma unroll
            for (int nt = 0; nt < 8; nt++) {
                int c0 = nt * 8 + tig * 2;
                if (c0     > lim1) s[nt][0] = -1e30f;
                if (c0 + 1 > lim1) s[nt][1] = -1e30f;
                if (c0     > lim2) s[nt][2] = -1e30f;
                if (c0 + 1 > lim2) s[nt][3] = -1e30f;
            }
        }

        float mx1 = -1e30f, mx2 = -1e30f;
#pragma unroll
        for (int nt = 0; nt < 8; nt++) {
            mx1 = fmaxf(mx1, fmaxf(s[nt][0], s[nt][1]));
            mx2 = fmaxf(mx2, fmaxf(s[nt][2], s[nt][3]));
        }
        mx1 = fmaxf(mx1, __shfl_xor_sync(0xffffffffu, mx1, 1));
        mx1 = fmaxf(mx1, __shfl_xor_sync(0xffffffffu, mx1, 2));
        mx2 = fmaxf(mx2, __shfl_xor_sync(0xffffffffu, mx2, 1));
        mx2 = fmaxf(mx2, __shfl_xor_sync(0xffffffffu, mx2, 2));

        const float mn1 = fmaxf(m1, mx1);
        const float mn2 = fmaxf(m2, mx2);
        const float al1 = __expf(m1 - mn1);
        const float al2 = __expf(m2 - mn2);

        float sm1 = 0.f, sm2 = 0.f;
#pragma unroll
        for (int nt = 0; nt < 8; nt++) {
            s[nt][0] = __expf(s[nt][0] - mn1);
            s[nt][1] = __expf(s[nt][1] - mn1);
            s[nt][2] = __expf(s[nt][2] - mn2);
            s[nt][3] = __expf(s[nt][3] - mn2);
            sm1 += s[nt][0] + s[nt][1];
            sm2 += s[nt][2] + s[nt][3];
        }
        sm1 += __shfl_xor_sync(0xffffffffu, sm1, 1);
        sm1 += __shfl_xor_sync(0xffffffffu, sm1, 2);
        sm2 += __shfl_xor_sync(0xffffffffu, sm2, 1);
        sm2 += __shfl_xor_sync(0xffffffffu, sm2, 2);

        l1 = al1 * l1 + sm1;
        l2 = al2 * l2 + sm2;
        m1 = mn1;
        m2 = mn2;

#pragma unroll
        for (int nt = 0; nt < 16; nt++) {
            o[nt][0] *= al1; o[nt][1] *= al1;
            o[nt][2] *= al2; o[nt][3] *= al2;
        }

        // write P (fp16) to warp-private Ps rows
#pragma unroll
        for (int nt = 0; nt < 8; nt++) {
            int c = nt * 8 + tig * 2;
            *(__half2*)(Ps + r1 * LDV + c) = __floats2half2_rn(s[nt][0], s[nt][1]);
            *(__half2*)(Ps + r2 * LDV + c) = __floats2half2_rn(s[nt][2], s[nt][3]);
        }
        __syncwarp();

        // ---- O += P @ V : warp 16 x 128, kv = 64 (4 x k16) ----
#pragma unroll
        for (int ks = 0; ks < 4; ks++) {
            uint32_t af[4];
            LDSM4(af[0], af[1], af[2], af[3], p_lm + ks * 32);
            const uint32_t vb = v_lm + ks * 32;
#pragma unroll
            for (int q = 0; q < 8; q++) {
                uint32_t b0, b1, b2, b3;
                LDSM4(b0, b1, b2, b3, vb + q * (16 * 144));
                uint32_t bfA[2] = { b0, b2 };
                uint32_t bfB[2] = { b1, b3 };
                mma16(o[2 * q],     af, bfA);
                mma16(o[2 * q + 1], af, bfB);
            }
        }
        __syncwarp();
    }

    const float inv1 = 1.f / l1;
    const float inv2 = 1.f / l2;
    __half* Og = out + ((size_t)b * SEQ + q0) * D_MODEL + h * D_HEAD;
#pragma unroll
    for (int nt = 0; nt < 16; nt++) {
        int c = nt * 8 + tig * 2;
        *(__half2*)(Og + (size_t)r1 * D_MODEL + c) =
            __floats2half2_rn(o[nt][0] * inv1, o[nt][1] * inv1);
        *(__half2*)(Og + (size_t)r2 * D_MODEL + c) =
            __floats2half2_rn(o[nt][2] * inv2, o[nt][3] * inv2);
    }
}

// ============================================================================
// Launch
// ============================================================================
extern "C" void kernel_launch(void* const* d_in, const int* in_sizes, int n_in,
                              void* d_out, int out_size) {
    const float* x    = (const float*)d_in[0];
    const float* Wqkv = (const float*)d_in[1];
    const float* bqkv = (const float*)d_in[2];
    const float* Wout = (const float*)d_in[3];
    const float* bout = (const float*)d_in[4];
    float* out = (float*)d_out;

    __half *qkv_p, *att_p, *xh_p, *wqkvT_p, *woutT_p;
    cudaGetSymbolAddress((void**)&qkv_p, g_qkv);
    cudaGetSymbolAddress((void**)&att_p, g_att);
    cudaGetSymbolAddress((void**)&xh_p, g_xh);
    cudaGetSymbolAddress((void**)&wqkvT_p, g_wqkvT);
    cudaGetSymbolAddress((void**)&woutT_p, g_woutT);

    cudaFuncSetAttribute(gemm_h, cudaFuncAttributeMaxDynamicSharedMemorySize,
                         (int)G_SMEM_BYTES);
    cudaFuncSetAttribute(attn_kernel, cudaFuncAttributeMaxDynamicSharedMemorySize,
                         (int)ATTN_SMEM_BYTES);

    // Prep: fp32 -> fp16 (x), transpose+convert (weights)
    {
        int n4 = BS * D_MODEL / 4;
        conv_half<<<(n4 + 255) / 256, 256>>>(x, xh_p, n4);
        transpose_half<<<dim3(QKV_N / 32, D_MODEL / 32), dim3(32, 8)>>>(Wqkv, wqkvT_p, D_MODEL, QKV_N);
        transpose_half<<<dim3(D_MODEL / 32, D_MODEL / 32), dim3(32, 8)>>>(Wout, woutT_p, D_MODEL, D_MODEL);
    }

    // 1) qkv = x @ W_qkv + b_qkv  [4096, 6144], fp16 out
    gemm_h<<<dim3(QKV_N / 128, BS / 128), 256, G_SMEM_BYTES>>>(
        xh_p, wqkvT_p, bqkv, nullptr, qkv_p, BS, QKV_N, D_MODEL, 1);

    // 2) causal flash attention -> g_att (fp16)
    attn_kernel<<<dim3(SEQ / 128, N_HEADS, BATCH), 256, ATTN_SMEM_BYTES>>>(qkv_p, att_p);

    // 3) out = att @ W_out + b_out  [4096, 2048], fp32 out
    gemm_h<<<dim3(D_MODEL / 128, BS / 128), 256, G_SMEM_BYTES>>>(
        att_p, woutT_p, bout, out, nullptr, BS, D_MODEL, D_MODEL, 0);
}